// round 11
// baseline (speedup 1.0000x reference)
#include <cuda_runtime.h>
#include <cuda_bf16.h>
#include <cstdint>

// out[b, o] = bias[o] + sum over UNIQUE (i0,i1) pairs in batch row b of
//             W[i0*350 + i1, o]
//
// Inputs (metadata order):
//   d_in[0]: x    int32  [32, 200, 3]   (b, i0, i1)
//   d_in[1]: W    float  [2150400, 5]
//   d_in[2]: b    float  [5]
// Output: float [32, 5]
//
// R8: R4 front half (224 threads, 1 hit/thread, speculative W gather
// overlapped with hash dedup) + shared-atomic epilogue replacing the
// shuffle tree / global-atomic drain / bias pre-init.

#define NB      32
#define NHITS   200
#define D1      350
#define OUT     5
#define TPB     224            // 7 warps
#define HASH_SZ 512
#define HASH_MASK (HASH_SZ - 1)

__global__ void __launch_bounds__(TPB, 1)
prtnn_kernel(const int* __restrict__ x,
             const float* __restrict__ W,
             const float* __restrict__ bias,
             float* __restrict__ out)
{
    const int b = blockIdx.x;
    const int t = threadIdx.x;

    __shared__ int   table[HASH_SZ];
    __shared__ float sacc[OUT];

    // Issue the x load FIRST so its latency overlaps table init + barrier.
    int f = -1;
    if (t < NHITS) {
        const int* xp = x + ((size_t)b * NHITS + t) * 3;
        f = __ldg(xp + 1) * D1 + __ldg(xp + 2);   // feature = i0*350 + i1
    }

    // bias into a register early (overlaps everything; used only at the end)
    float bv = (t < OUT) ? __ldg(bias + t) : 0.0f;

    // hash-table init (stride loop) + output accumulators
    #pragma unroll
    for (int s = t; s < HASH_SZ; s += TPB) table[s] = -1;
    if (t < OUT) sacc[t] = 0.0f;

    __syncthreads();

    if (t < NHITS) {
        // Speculatively issue the W-row gather NOW (idempotent) so its memory
        // latency overlaps with the hash-based dedup below.
        const float* w = W + f * OUT;             // f*5 < 10.75M, fits int32
        float wv[OUT];
        #pragma unroll
        for (int o = 0; o < OUT; ++o) wv[o] = __ldg(w + o);

        // hash-set insert: winner of the CAS for feature f is "unique".
        unsigned slot = ((unsigned)f * 0x9E3779B1u >> 23) & HASH_MASK;
        int prev = atomicCAS(&table[slot], -1, f);
        while (prev != -1 && prev != f) {
            slot = (slot + 1) & HASH_MASK;
            prev = atomicCAS(&table[slot], -1, f);
        }

        // first occurrence only: accumulate into shared (5 distinct banks)
        if (prev == -1) {
            #pragma unroll
            for (int o = 0; o < OUT; ++o)
                atomicAdd(&sacc[o], wv[o]);
        }
    }

    __syncthreads();

    // threads 0..4 emit bias + total; single cheap STG tail
    if (t < OUT) {
        out[b * OUT + t] = bv + sacc[t];
    }
}

extern "C" void kernel_launch(void* const* d_in, const int* in_sizes, int n_in,
                              void* d_out, int out_size)
{
    const int*   x    = (const int*)d_in[0];
    const float* W    = (const float*)d_in[1];
    const float* bias = (const float*)d_in[2];
    float*       out  = (float*)d_out;

    prtnn_kernel<<<NB, TPB>>>(x, W, bias, out);
}

// round 17
// speedup vs baseline: 3.7508x; 3.7508x over previous
#include <cuda_runtime.h>
#include <cuda_bf16.h>
#include <cstdint>

// out[b, o] = bias[o] + sum over UNIQUE (i0,i1) pairs in batch row b of
//             W[i0*350 + i1, o]
//
// Inputs (metadata order):
//   d_in[0]: x    int32  [32, 200, 3]   (b, i0, i1)
//   d_in[1]: W    float  [2150400, 5]
//   d_in[2]: b    float  [5]
// Output: float [32, 5]
//
// R12 = R4 (measured best, 8.96us) with butterfly reduce + lane-distributed
// epilogue atomics (one REDG per lane 0..4 per warp instead of 5 from lane 0).
// R8's bulk shared-memory atomics are reverted (measured 4x regression).

#define NB      32
#define NHITS   200
#define D1      350
#define OUT     5
#define TPB     224            // 7 warps
#define HASH_SZ 512
#define HASH_MASK (HASH_SZ - 1)

__global__ void __launch_bounds__(TPB, 1)
prtnn_kernel(const int* __restrict__ x,
             const float* __restrict__ W,
             const float* __restrict__ bias,
             float* __restrict__ out)
{
    const int b = blockIdx.x;
    const int t = threadIdx.x;

    __shared__ int table[HASH_SZ];

    // Issue the x load FIRST so its latency overlaps table init + barrier.
    int f = -1;
    if (t < NHITS) {
        const int* xp = x + ((size_t)b * NHITS + t) * 3;
        f = __ldg(xp + 1) * D1 + __ldg(xp + 2);   // feature = i0*350 + i1
    }

    // hash-table init (scalar stride loop — int4 variant measured slower)
    #pragma unroll
    for (int s = t; s < HASH_SZ; s += TPB) table[s] = -1;

    // initialize this block's 5 outputs with the bias (ordered before the
    // epilogue atomics by the __syncthreads cta-scope fence)
    if (t < OUT) out[b * OUT + t] = __ldg(bias + t);

    __syncthreads();

    float acc[OUT] = {0.f, 0.f, 0.f, 0.f, 0.f};
    if (t < NHITS) {
        // Speculatively issue the W-row gather NOW (idempotent) so its memory
        // latency overlaps with the hash-based dedup below.
        const float* w = W + f * OUT;             // f*5 < 10.75M, fits int32
        float wv[OUT];
        #pragma unroll
        for (int o = 0; o < OUT; ++o) wv[o] = __ldg(w + o);

        // hash-set insert: winner of the CAS for feature f is "unique".
        unsigned slot = ((unsigned)f * 0x9E3779B1u >> 23) & HASH_MASK;
        int prev = atomicCAS(&table[slot], -1, f);
        while (prev != -1 && prev != f) {
            slot = (slot + 1) & HASH_MASK;
            prev = atomicCAS(&table[slot], -1, f);
        }
        const float m = (prev == -1) ? 1.0f : 0.0f;   // first occurrence only
        #pragma unroll
        for (int o = 0; o < OUT; ++o) acc[o] = wv[o] * m;
    }

    // butterfly reduce: every lane ends with all 5 warp totals
    #pragma unroll
    for (int off = 16; off > 0; off >>= 1) {
        #pragma unroll
        for (int o = 0; o < OUT; ++o)
            acc[o] += __shfl_xor_sync(0xFFFFFFFFu, acc[o], off);
    }

    // lanes 0..4 of each warp each issue ONE global atomic (parallel issue,
    // overlapping drains; out was bias-initialized before the barrier)
    const int lane = t & 31;
    if (lane < OUT) {
        float v = acc[0];
        #pragma unroll
        for (int o = 1; o < OUT; ++o)
            if (o == lane) v = acc[o];
        atomicAdd(&out[b * OUT + lane], v);
    }
}

extern "C" void kernel_launch(void* const* d_in, const int* in_sizes, int n_in,
                              void* d_out, int out_size)
{
    const int*   x    = (const int*)d_in[0];
    const float* W    = (const float*)d_in[1];
    const float* bias = (const float*)d_in[2];
    float*       out  = (float*)d_out;

    prtnn_kernel<<<NB, TPB>>>(x, W, bias, out);
}